// round 1
// baseline (speedup 1.0000x reference)
#include <cuda_runtime.h>
#include <float.h>
#include <math.h>

#define B_     2
#define RESO_  32
#define G_     (RESO_*RESO_*RESO_)     /* 32768 */
#define BG_    (B_*G_)                 /* 65536 */
#define HID_   32
#define NMAX_  524288
#define BDIM   128

/* -------- scratch (static device globals: allocation-free) -------- */
__device__ float g_net[(size_t)NMAX_*HID_];   /* 64 MB */
__device__ int   g_gidx[NMAX_];
__device__ float g_cellA[BG_*HID_];           /* 8 MB */
__device__ float g_cellB[BG_*HID_];
__device__ float g_sums[BG_*HID_];
__device__ float g_cnt[BG_];

__device__ __forceinline__ void atomicMaxFloat(float* addr, float v) {
    v += 0.0f;                       /* canonicalize -0 -> +0 */
    if (v >= 0.0f) atomicMax((int*)addr, __float_as_int(v));
    else           atomicMin((unsigned int*)addr, __float_as_uint(v));
}

/* -------- init kernels -------- */
__global__ void init_cells_kernel(int which) {
    float* ptr = which ? g_cellB : g_cellA;
    int stride = gridDim.x * blockDim.x;
    for (int i = blockIdx.x*blockDim.x + threadIdx.x; i < BG_*HID_; i += stride)
        ptr[i] = -FLT_MAX;
}

__global__ void clear_accum_kernel() {
    int stride = gridDim.x * blockDim.x;
    for (int i = blockIdx.x*blockDim.x + threadIdx.x; i < BG_*HID_; i += stride)
        g_sums[i] = 0.0f;
    for (int i = blockIdx.x*blockDim.x + threadIdx.x; i < BG_; i += stride)
        g_cnt[i] = 0.0f;
}

/* -------- residual block: x(64, smem transposed) -> out(32, regs) --------
   h = relu( relu(x) @ W0 + b0 );  out = x @ Ws + ( h @ W1 + b1 )
   sx is mutated (rows 0..31 reused to stage relu(h)). */
__device__ __forceinline__ void resblock_body(
    float* sx, int tid,
    const float* __restrict__ sW0, const float* __restrict__ sB0,
    const float* __restrict__ sW1, const float* __restrict__ sB1,
    const float* __restrict__ sWs,
    float* out)
{
    float h[HID_];
#pragma unroll
    for (int j = 0; j < HID_; j++) { h[j] = sB0[j]; out[j] = sB1[j]; }

#pragma unroll 4
    for (int k = 0; k < 64; k++) {
        float xk = sx[k*BDIM + tid];
        float xr = fmaxf(xk, 0.0f);
        const float4* r0 = reinterpret_cast<const float4*>(sW0 + k*HID_);
        const float4* rs = reinterpret_cast<const float4*>(sWs + k*HID_);
#pragma unroll
        for (int j = 0; j < 8; j++) {
            float4 a = r0[j], s = rs[j];
            h[4*j+0] += xr*a.x;  h[4*j+1] += xr*a.y;  h[4*j+2] += xr*a.z;  h[4*j+3] += xr*a.w;
            out[4*j+0] += xk*s.x; out[4*j+1] += xk*s.y; out[4*j+2] += xk*s.z; out[4*j+3] += xk*s.w;
        }
    }
    /* stage relu(h) into sx rows 0..31 (x fully consumed) to allow dynamic k */
#pragma unroll
    for (int j = 0; j < HID_; j++) sx[j*BDIM + tid] = fmaxf(h[j], 0.0f);

#pragma unroll 4
    for (int k = 0; k < HID_; k++) {
        float hk = sx[k*BDIM + tid];
        const float4* r1 = reinterpret_cast<const float4*>(sW1 + k*HID_);
#pragma unroll
        for (int j = 0; j < 8; j++) {
            float4 a = r1[j];
            out[4*j+0] += hk*a.x; out[4*j+1] += hk*a.y; out[4*j+2] += hk*a.z; out[4*j+3] += hk*a.w;
        }
    }
}

/* -------- stage 0: PE + fc_pos + resblock0 + scatter-max into cellA -------- */
__global__ void __launch_bounds__(BDIM) point0_kernel(
    const float* __restrict__ p,
    const float* __restrict__ Wp, const float* __restrict__ Bp,
    const float* __restrict__ w0, const float* __restrict__ b0,
    const float* __restrict__ w1, const float* __restrict__ b1,
    const float* __restrict__ ws,
    int T, int N)
{
    extern __shared__ float smem[];
    float* sWp = smem;                 /* 60*64 = 3840 */
    float* sW0 = sWp + 60*64;          /* 2048 */
    float* sWs = sW0 + 64*HID_;        /* 2048 */
    float* sW1 = sWs + 64*HID_;        /* 1024 */
    float* sBp = sW1 + HID_*HID_;      /* 64 */
    float* sB0 = sBp + 64;             /* 32 */
    float* sB1 = sB0 + HID_;           /* 32 */
    float* sx  = sB1 + HID_;           /* 64*BDIM */

    for (int t = threadIdx.x; t < 60*64; t += BDIM) sWp[t] = Wp[t];
    for (int t = threadIdx.x; t < 64*HID_; t += BDIM) { sW0[t] = w0[t]; sWs[t] = ws[t]; }
    for (int t = threadIdx.x; t < HID_*HID_; t += BDIM) sW1[t] = w1[t];
    for (int t = threadIdx.x; t < 64; t += BDIM) sBp[t] = Bp[t];
    for (int t = threadIdx.x; t < HID_; t += BDIM) { sB0[t] = b0[t]; sB1[t] = b1[t]; }
    __syncthreads();

    int i = blockIdx.x*BDIM + threadIdx.x;
    if (i >= N) return;
    int tid = threadIdx.x;

    float p0 = p[3*i+0], p1 = p[3*i+1], p2 = p[3*i+2];

    /* voxel index (match reference rounding exactly: IEEE div) */
    int b = i / T;
    float pn0 = fminf(fmaxf(__fdiv_rn(p0, 1.101f) + 0.5f, 0.0f), 0.999f);
    float pn1 = fminf(fmaxf(__fdiv_rn(p1, 1.101f) + 0.5f, 0.0f), 0.999f);
    float pn2 = fminf(fmaxf(__fdiv_rn(p2, 1.101f) + 0.5f, 0.0f), 0.999f);
    int xi0 = (int)floorf(pn0 * 32.0f);
    int xi1 = (int)floorf(pn1 * 32.0f);
    int xi2 = (int)floorf(pn2 * 32.0f);
    int gidx = xi0 + RESO_*(xi1 + RESO_*xi2) + b*G_;
    g_gidx[i] = gidx;

    /* x = PE(p) @ Wp + Bp  -- fold sin/cos directly into the GEMV */
    float x[64];
#pragma unroll
    for (int j = 0; j < 64; j++) x[j] = sBp[j];

    float q[3] = {2.0f*p0 - 1.0f, 2.0f*p1 - 1.0f, 2.0f*p2 - 1.0f};
#pragma unroll
    for (int d = 0; d < 3; d++) {
        float y = q[d];
#pragma unroll 1
        for (int l = 0; l < 10; l++) {
            float s, c;
            sincospif(y, &s, &c);   /* sin(pi * q * 2^l), exact range reduction */
            const float4* rs_ = reinterpret_cast<const float4*>(sWp + (l*6 + d)*64);
            const float4* rc_ = reinterpret_cast<const float4*>(sWp + (l*6 + 3 + d)*64);
#pragma unroll
            for (int j = 0; j < 16; j++) {
                float4 a = rs_[j], bb = rc_[j];
                x[4*j+0] += s*a.x + c*bb.x;
                x[4*j+1] += s*a.y + c*bb.y;
                x[4*j+2] += s*a.z + c*bb.z;
                x[4*j+3] += s*a.w + c*bb.w;
            }
            y *= 2.0f;
        }
    }

#pragma unroll
    for (int j = 0; j < 64; j++) sx[j*BDIM + tid] = x[j];

    float out[HID_];
    resblock_body(sx, tid, sW0, sB0, sW1, sB1, sWs, out);

    float4* nw = reinterpret_cast<float4*>(&g_net[(size_t)i*HID_]);
#pragma unroll
    for (int j = 0; j < 8; j++)
        nw[j] = make_float4(out[4*j], out[4*j+1], out[4*j+2], out[4*j+3]);

    float* cd = &g_cellA[gidx*HID_];
#pragma unroll
    for (int j = 0; j < HID_; j++) atomicMaxFloat(cd + j, out[j]);
}

/* -------- stages 1..3: gather pooled + resblock + scatter-max -------- */
__global__ void __launch_bounds__(BDIM) pool_block_kernel(
    const float* __restrict__ w0, const float* __restrict__ b0,
    const float* __restrict__ w1, const float* __restrict__ b1,
    const float* __restrict__ ws,
    int srcA, int N)
{
    extern __shared__ float smem[];
    float* sW0 = smem;
    float* sWs = sW0 + 64*HID_;
    float* sW1 = sWs + 64*HID_;
    float* sB0 = sW1 + HID_*HID_;
    float* sB1 = sB0 + HID_;
    float* sx  = sB1 + HID_;

    for (int t = threadIdx.x; t < 64*HID_; t += BDIM) { sW0[t] = w0[t]; sWs[t] = ws[t]; }
    for (int t = threadIdx.x; t < HID_*HID_; t += BDIM) sW1[t] = w1[t];
    for (int t = threadIdx.x; t < HID_; t += BDIM) { sB0[t] = b0[t]; sB1[t] = b1[t]; }
    __syncthreads();

    int i = blockIdx.x*BDIM + threadIdx.x;
    if (i >= N) return;
    int tid = threadIdx.x;
    int gidx = g_gidx[i];

    const float* cellSrc = srcA ? g_cellA : g_cellB;
    float*       cellDst = srcA ? g_cellB : g_cellA;

    const float4* np = reinterpret_cast<const float4*>(&g_net[(size_t)i*HID_]);
    const float4* pp = reinterpret_cast<const float4*>(&cellSrc[gidx*HID_]);
#pragma unroll
    for (int j = 0; j < 8; j++) {
        float4 a = np[j];
        sx[(4*j+0)*BDIM + tid] = a.x; sx[(4*j+1)*BDIM + tid] = a.y;
        sx[(4*j+2)*BDIM + tid] = a.z; sx[(4*j+3)*BDIM + tid] = a.w;
        float4 pb = pp[j];
        sx[(32+4*j+0)*BDIM + tid] = pb.x; sx[(32+4*j+1)*BDIM + tid] = pb.y;
        sx[(32+4*j+2)*BDIM + tid] = pb.z; sx[(32+4*j+3)*BDIM + tid] = pb.w;
    }

    float out[HID_];
    resblock_body(sx, tid, sW0, sB0, sW1, sB1, sWs, out);

    float4* nw = reinterpret_cast<float4*>(&g_net[(size_t)i*HID_]);
#pragma unroll
    for (int j = 0; j < 8; j++)
        nw[j] = make_float4(out[4*j], out[4*j+1], out[4*j+2], out[4*j+3]);

    float* cd = &cellDst[gidx*HID_];
#pragma unroll
    for (int j = 0; j < HID_; j++) atomicMaxFloat(cd + j, out[j]);
}

/* -------- stage 4: gather + resblock4 + fc_c + scatter-mean accum -------- */
__global__ void __launch_bounds__(BDIM) final_kernel(
    const float* __restrict__ w0, const float* __restrict__ b0,
    const float* __restrict__ w1, const float* __restrict__ b1,
    const float* __restrict__ ws,
    const float* __restrict__ fcw, const float* __restrict__ fcb,
    int srcA, int N)
{
    extern __shared__ float smem[];
    float* sW0 = smem;
    float* sWs = sW0 + 64*HID_;
    float* sW1 = sWs + 64*HID_;
    float* sFc = sW1 + HID_*HID_;      /* 32*32 */
    float* sB0 = sFc + HID_*HID_;
    float* sB1 = sB0 + HID_;
    float* sFb = sB1 + HID_;
    float* sx  = sFb + HID_;

    for (int t = threadIdx.x; t < 64*HID_; t += BDIM) { sW0[t] = w0[t]; sWs[t] = ws[t]; }
    for (int t = threadIdx.x; t < HID_*HID_; t += BDIM) { sW1[t] = w1[t]; sFc[t] = fcw[t]; }
    for (int t = threadIdx.x; t < HID_; t += BDIM) { sB0[t] = b0[t]; sB1[t] = b1[t]; sFb[t] = fcb[t]; }
    __syncthreads();

    int i = blockIdx.x*BDIM + threadIdx.x;
    if (i >= N) return;
    int tid = threadIdx.x;
    int gidx = g_gidx[i];

    const float* cellSrc = srcA ? g_cellA : g_cellB;

    const float4* np = reinterpret_cast<const float4*>(&g_net[(size_t)i*HID_]);
    const float4* pp = reinterpret_cast<const float4*>(&cellSrc[gidx*HID_]);
#pragma unroll
    for (int j = 0; j < 8; j++) {
        float4 a = np[j];
        sx[(4*j+0)*BDIM + tid] = a.x; sx[(4*j+1)*BDIM + tid] = a.y;
        sx[(4*j+2)*BDIM + tid] = a.z; sx[(4*j+3)*BDIM + tid] = a.w;
        float4 pb = pp[j];
        sx[(32+4*j+0)*BDIM + tid] = pb.x; sx[(32+4*j+1)*BDIM + tid] = pb.y;
        sx[(32+4*j+2)*BDIM + tid] = pb.z; sx[(32+4*j+3)*BDIM + tid] = pb.w;
    }

    float out[HID_];
    resblock_body(sx, tid, sW0, sB0, sW1, sB1, sWs, out);

    /* c = out @ fc_c_w + fc_c_b */
#pragma unroll
    for (int j = 0; j < HID_; j++) sx[j*BDIM + tid] = out[j];
    float cv[HID_];
#pragma unroll
    for (int j = 0; j < HID_; j++) cv[j] = sFb[j];
#pragma unroll 4
    for (int k = 0; k < HID_; k++) {
        float ok = sx[k*BDIM + tid];
        const float4* r = reinterpret_cast<const float4*>(sFc + k*HID_);
#pragma unroll
        for (int j = 0; j < 8; j++) {
            float4 a = r[j];
            cv[4*j+0] += ok*a.x; cv[4*j+1] += ok*a.y; cv[4*j+2] += ok*a.z; cv[4*j+3] += ok*a.w;
        }
    }

    float* sp = &g_sums[gidx*HID_];
#pragma unroll
    for (int j = 0; j < HID_; j++) atomicAdd(sp + j, cv[j]);
    atomicAdd(&g_cnt[gidx], 1.0f);
}

/* -------- output: mean + transpose to [B, CDIM, G] -------- */
__global__ void output_kernel(float* __restrict__ out, int total) {
    int t = blockIdx.x*blockDim.x + threadIdx.x;
    if (t >= total) return;
    int g = t & (G_ - 1);
    int c = (t >> 15) & (HID_ - 1);
    int b = t >> 20;
    int bg = b*G_ + g;
    float cnt = fmaxf(g_cnt[bg], 1.0f);
    out[t] = g_sums[bg*HID_ + c] / cnt;
}

/* -------- host launcher -------- */
extern "C" void kernel_launch(void* const* d_in, const int* in_sizes, int n_in,
                              void* d_out, int out_size) {
    const float* p   = (const float*)d_in[0];
    const float* Wp  = (const float*)d_in[1];
    const float* Bp  = (const float*)d_in[2];
    const float* W0  = (const float*)d_in[3];
    const float* B0  = (const float*)d_in[4];
    const float* W1  = (const float*)d_in[5];
    const float* B1  = (const float*)d_in[6];
    const float* Ws  = (const float*)d_in[7];
    const float* Fc  = (const float*)d_in[8];
    const float* FcB = (const float*)d_in[9];
    float* out = (float*)d_out;

    int T = in_sizes[0] / (B_ * 3);
    int N = B_ * T;
    int nb = (N + BDIM - 1) / BDIM;

    const int P0_SMEM = (3840 + 2048 + 2048 + 1024 + 64 + 32 + 32 + 64*BDIM) * 4;
    const int PB_SMEM = (2048 + 2048 + 1024 + 32 + 32 + 64*BDIM) * 4;
    const int PF_SMEM = (2048 + 2048 + 1024 + 1024 + 32 + 32 + 32 + 64*BDIM) * 4;

    cudaFuncSetAttribute(point0_kernel, cudaFuncAttributeMaxDynamicSharedMemorySize, P0_SMEM);
    cudaFuncSetAttribute(pool_block_kernel, cudaFuncAttributeMaxDynamicSharedMemorySize, PB_SMEM);
    cudaFuncSetAttribute(final_kernel, cudaFuncAttributeMaxDynamicSharedMemorySize, PF_SMEM);

    /* block 0 + scatter into A */
    init_cells_kernel<<<512, 256>>>(0);
    point0_kernel<<<nb, BDIM, P0_SMEM>>>(p, Wp, Bp, W0, B0, W1, B1, Ws, T, N);

    /* block 1: read A -> write B */
    init_cells_kernel<<<512, 256>>>(1);
    pool_block_kernel<<<nb, BDIM, PB_SMEM>>>(W0 + 1*64*HID_, B0 + 1*HID_,
                                             W1 + 1*HID_*HID_, B1 + 1*HID_,
                                             Ws + 1*64*HID_, 1, N);
    /* block 2: read B -> write A */
    init_cells_kernel<<<512, 256>>>(0);
    pool_block_kernel<<<nb, BDIM, PB_SMEM>>>(W0 + 2*64*HID_, B0 + 2*HID_,
                                             W1 + 2*HID_*HID_, B1 + 2*HID_,
                                             Ws + 2*64*HID_, 0, N);
    /* block 3: read A -> write B */
    init_cells_kernel<<<512, 256>>>(1);
    pool_block_kernel<<<nb, BDIM, PB_SMEM>>>(W0 + 3*64*HID_, B0 + 3*HID_,
                                             W1 + 3*HID_*HID_, B1 + 3*HID_,
                                             Ws + 3*64*HID_, 1, N);
    /* block 4 + fc_c + scatter-mean: read B */
    clear_accum_kernel<<<512, 256>>>();
    final_kernel<<<nb, BDIM, PF_SMEM>>>(W0 + 4*64*HID_, B0 + 4*HID_,
                                        W1 + 4*HID_*HID_, B1 + 4*HID_,
                                        Ws + 4*64*HID_, Fc, FcB, 0, N);

    output_kernel<<<(out_size + 255)/256, 256>>>(out, out_size);
}

// round 2
// speedup vs baseline: 1.0363x; 1.0363x over previous
#include <cuda_runtime.h>
#include <float.h>
#include <math.h>

#define B_     2
#define RESO_  32
#define G_     (RESO_*RESO_*RESO_)     /* 32768 */
#define BG_    (B_*G_)                 /* 65536 */
#define HID_   32
#define NMAX_  524288
#define BDIM   128

typedef unsigned long long u64;

/* -------- packed f32x2 helpers (Blackwell FFMA2 path) -------- */
__device__ __forceinline__ u64 splat2(float v) {
    u64 r; asm("mov.b64 %0, {%1, %1};" : "=l"(r) : "f"(v)); return r;
}
__device__ __forceinline__ void unpack2(u64 v, float& lo, float& hi) {
    asm("mov.b64 {%0, %1}, %2;" : "=f"(lo), "=f"(hi) : "l"(v));
}
__device__ __forceinline__ void ffma2(u64& d, u64 a, u64 b) {
    asm("fma.rn.f32x2 %0, %1, %2, %0;" : "+l"(d) : "l"(a), "l"(b));
}

/* -------- scratch (static device globals: allocation-free) -------- */
__device__ float g_net[(size_t)NMAX_*HID_];   /* 64 MB */
__device__ int   g_gidx[NMAX_];
__device__ float g_cellA[BG_*HID_];           /* 8 MB */
__device__ float g_cellB[BG_*HID_];
__device__ float g_sums[BG_*HID_];
__device__ float g_cnt[BG_];

__device__ __forceinline__ void atomicMaxFloat(float* addr, float v) {
    v += 0.0f;                       /* canonicalize -0 -> +0 */
    if (v >= 0.0f) atomicMax((int*)addr, __float_as_int(v));
    else           atomicMin((unsigned int*)addr, __float_as_uint(v));
}

/* -------- init kernels -------- */
__global__ void init_cells_kernel(int which) {
    float* ptr = which ? g_cellB : g_cellA;
    int stride = gridDim.x * blockDim.x;
    for (int i = blockIdx.x*blockDim.x + threadIdx.x; i < BG_*HID_; i += stride)
        ptr[i] = -FLT_MAX;
}

__global__ void clear_accum_kernel() {
    int stride = gridDim.x * blockDim.x;
    for (int i = blockIdx.x*blockDim.x + threadIdx.x; i < BG_*HID_; i += stride)
        g_sums[i] = 0.0f;
    for (int i = blockIdx.x*blockDim.x + threadIdx.x; i < BG_; i += stride)
        g_cnt[i] = 0.0f;
}

/* -------- residual block (packed f32x2): x(64, smem transposed) -> out(32)
   h = relu( relu(x) @ W0 + b0 );  out = x @ Ws + ( h @ W1 + b1 )              */
__device__ __forceinline__ void resblock_f32x2(
    const float* sx, int tid,
    const float* __restrict__ sW0, const float* __restrict__ sB0,
    const float* __restrict__ sW1, const float* __restrict__ sB1,
    const float* __restrict__ sWs,
    float* out)
{
    u64 h2[16], o2[16];
    const u64* b0p = reinterpret_cast<const u64*>(sB0);
    const u64* b1p = reinterpret_cast<const u64*>(sB1);
#pragma unroll
    for (int j = 0; j < 16; j++) { h2[j] = b0p[j]; o2[j] = b1p[j]; }

#pragma unroll 4
    for (int k = 0; k < 64; k++) {
        float xk = sx[k*BDIM + tid];
        u64 xk2 = splat2(xk);
        u64 xr2 = splat2(fmaxf(xk, 0.0f));
        const ulonglong2* r0 = reinterpret_cast<const ulonglong2*>(sW0 + k*HID_);
        const ulonglong2* rs = reinterpret_cast<const ulonglong2*>(sWs + k*HID_);
#pragma unroll
        for (int j = 0; j < 8; j++) {
            ulonglong2 a = r0[j], s = rs[j];
            ffma2(h2[2*j+0], xr2, a.x);
            ffma2(h2[2*j+1], xr2, a.y);
            ffma2(o2[2*j+0], xk2, s.x);
            ffma2(o2[2*j+1], xk2, s.y);
        }
    }

    /* relu(h) stays in registers; W1 GEMV fully unrolled (no smem round-trip) */
    float hr[HID_];
#pragma unroll
    for (int j = 0; j < 16; j++) {
        float lo, hi; unpack2(h2[j], lo, hi);
        hr[2*j+0] = fmaxf(lo, 0.0f);
        hr[2*j+1] = fmaxf(hi, 0.0f);
    }
#pragma unroll
    for (int k = 0; k < HID_; k++) {
        u64 hk2 = splat2(hr[k]);
        const ulonglong2* r1 = reinterpret_cast<const ulonglong2*>(sW1 + k*HID_);
#pragma unroll
        for (int j = 0; j < 8; j++) {
            ulonglong2 a = r1[j];
            ffma2(o2[2*j+0], hk2, a.x);
            ffma2(o2[2*j+1], hk2, a.y);
        }
    }
#pragma unroll
    for (int j = 0; j < 16; j++) unpack2(o2[j], out[2*j], out[2*j+1]);
}

/* -------- stage 0: PE + fc_pos + resblock0 + scatter-max into cellA -------- */
__global__ void __launch_bounds__(BDIM) point0_kernel(
    const float* __restrict__ p,
    const float* __restrict__ Wp, const float* __restrict__ Bp,
    const float* __restrict__ w0, const float* __restrict__ b0,
    const float* __restrict__ w1, const float* __restrict__ b1,
    const float* __restrict__ ws,
    int T, int N)
{
    extern __shared__ float smem[];
    float* sWp = smem;                 /* 60*64 = 3840 */
    float* sW0 = sWp + 60*64;          /* 2048 */
    float* sWs = sW0 + 64*HID_;        /* 2048 */
    float* sW1 = sWs + 64*HID_;        /* 1024 */
    float* sBp = sW1 + HID_*HID_;      /* 64 */
    float* sB0 = sBp + 64;             /* 32 */
    float* sB1 = sB0 + HID_;           /* 32 */
    float* sx  = sB1 + HID_;           /* 64*BDIM */

    for (int t = threadIdx.x; t < 60*64; t += BDIM) sWp[t] = Wp[t];
    for (int t = threadIdx.x; t < 64*HID_; t += BDIM) { sW0[t] = w0[t]; sWs[t] = ws[t]; }
    for (int t = threadIdx.x; t < HID_*HID_; t += BDIM) sW1[t] = w1[t];
    for (int t = threadIdx.x; t < 64; t += BDIM) sBp[t] = Bp[t];
    for (int t = threadIdx.x; t < HID_; t += BDIM) { sB0[t] = b0[t]; sB1[t] = b1[t]; }
    __syncthreads();

    int i = blockIdx.x*BDIM + threadIdx.x;
    if (i >= N) return;
    int tid = threadIdx.x;

    float p0 = p[3*i+0], p1 = p[3*i+1], p2 = p[3*i+2];

    /* voxel index (match reference rounding exactly: IEEE div) */
    int b = i / T;
    float pn0 = fminf(fmaxf(__fdiv_rn(p0, 1.101f) + 0.5f, 0.0f), 0.999f);
    float pn1 = fminf(fmaxf(__fdiv_rn(p1, 1.101f) + 0.5f, 0.0f), 0.999f);
    float pn2 = fminf(fmaxf(__fdiv_rn(p2, 1.101f) + 0.5f, 0.0f), 0.999f);
    int xi0 = (int)floorf(pn0 * 32.0f);
    int xi1 = (int)floorf(pn1 * 32.0f);
    int xi2 = (int)floorf(pn2 * 32.0f);
    int gidx = xi0 + RESO_*(xi1 + RESO_*xi2) + b*G_;
    g_gidx[i] = gidx;

    /* x = PE(p) @ Wp + Bp -- fold sin/cos into the GEMV, packed accum */
    u64 x2[32];
    const u64* bp2 = reinterpret_cast<const u64*>(sBp);
#pragma unroll
    for (int j = 0; j < 32; j++) x2[j] = bp2[j];

    float q[3] = {2.0f*p0 - 1.0f, 2.0f*p1 - 1.0f, 2.0f*p2 - 1.0f};
#pragma unroll
    for (int d = 0; d < 3; d++) {
        float y = q[d];
#pragma unroll 1
        for (int l = 0; l < 10; l++) {
            float s, c;
            sincospif(y, &s, &c);   /* sin(pi * q * 2^l), exact range reduction */
            u64 s2 = splat2(s), c2 = splat2(c);
            const ulonglong2* rs_ = reinterpret_cast<const ulonglong2*>(sWp + (l*6 + d)*64);
            const ulonglong2* rc_ = reinterpret_cast<const ulonglong2*>(sWp + (l*6 + 3 + d)*64);
#pragma unroll
            for (int j = 0; j < 16; j++) {
                ulonglong2 a = rs_[j], bb = rc_[j];
                ffma2(x2[2*j+0], s2, a.x);
                ffma2(x2[2*j+1], s2, a.y);
                ffma2(x2[2*j+0], c2, bb.x);
                ffma2(x2[2*j+1], c2, bb.y);
            }
            y *= 2.0f;
        }
    }

#pragma unroll
    for (int j = 0; j < 32; j++) {
        float lo, hi; unpack2(x2[j], lo, hi);
        sx[(2*j+0)*BDIM + tid] = lo;
        sx[(2*j+1)*BDIM + tid] = hi;
    }

    float out[HID_];
    resblock_f32x2(sx, tid, sW0, sB0, sW1, sB1, sWs, out);

    float4* nw = reinterpret_cast<float4*>(&g_net[(size_t)i*HID_]);
#pragma unroll
    for (int j = 0; j < 8; j++)
        nw[j] = make_float4(out[4*j], out[4*j+1], out[4*j+2], out[4*j+3]);

    float* cd = &g_cellA[gidx*HID_];
#pragma unroll
    for (int j = 0; j < HID_; j++) atomicMaxFloat(cd + j, out[j]);
}

/* -------- stages 1..3: gather pooled + resblock + scatter-max -------- */
__global__ void __launch_bounds__(BDIM) pool_block_kernel(
    const float* __restrict__ w0, const float* __restrict__ b0,
    const float* __restrict__ w1, const float* __restrict__ b1,
    const float* __restrict__ ws,
    int srcA, int N)
{
    extern __shared__ float smem[];
    float* sW0 = smem;
    float* sWs = sW0 + 64*HID_;
    float* sW1 = sWs + 64*HID_;
    float* sB0 = sW1 + HID_*HID_;
    float* sB1 = sB0 + HID_;
    float* sx  = sB1 + HID_;

    for (int t = threadIdx.x; t < 64*HID_; t += BDIM) { sW0[t] = w0[t]; sWs[t] = ws[t]; }
    for (int t = threadIdx.x; t < HID_*HID_; t += BDIM) sW1[t] = w1[t];
    for (int t = threadIdx.x; t < HID_; t += BDIM) { sB0[t] = b0[t]; sB1[t] = b1[t]; }
    __syncthreads();

    int i = blockIdx.x*BDIM + threadIdx.x;
    if (i >= N) return;
    int tid = threadIdx.x;
    int gidx = g_gidx[i];

    const float* cellSrc = srcA ? g_cellA : g_cellB;
    float*       cellDst = srcA ? g_cellB : g_cellA;

    const float4* np = reinterpret_cast<const float4*>(&g_net[(size_t)i*HID_]);
    const float4* pp = reinterpret_cast<const float4*>(&cellSrc[gidx*HID_]);
#pragma unroll
    for (int j = 0; j < 8; j++) {
        float4 a = np[j];
        sx[(4*j+0)*BDIM + tid] = a.x; sx[(4*j+1)*BDIM + tid] = a.y;
        sx[(4*j+2)*BDIM + tid] = a.z; sx[(4*j+3)*BDIM + tid] = a.w;
        float4 pb = pp[j];
        sx[(32+4*j+0)*BDIM + tid] = pb.x; sx[(32+4*j+1)*BDIM + tid] = pb.y;
        sx[(32+4*j+2)*BDIM + tid] = pb.z; sx[(32+4*j+3)*BDIM + tid] = pb.w;
    }

    float out[HID_];
    resblock_f32x2(sx, tid, sW0, sB0, sW1, sB1, sWs, out);

    float4* nw = reinterpret_cast<float4*>(&g_net[(size_t)i*HID_]);
#pragma unroll
    for (int j = 0; j < 8; j++)
        nw[j] = make_float4(out[4*j], out[4*j+1], out[4*j+2], out[4*j+3]);

    float* cd = &cellDst[gidx*HID_];
#pragma unroll
    for (int j = 0; j < HID_; j++) atomicMaxFloat(cd + j, out[j]);
}

/* -------- stage 4: gather + resblock4 + fc_c + scatter-mean accum -------- */
__global__ void __launch_bounds__(BDIM) final_kernel(
    const float* __restrict__ w0, const float* __restrict__ b0,
    const float* __restrict__ w1, const float* __restrict__ b1,
    const float* __restrict__ ws,
    const float* __restrict__ fcw, const float* __restrict__ fcb,
    int srcA, int N)
{
    extern __shared__ float smem[];
    float* sW0 = smem;
    float* sWs = sW0 + 64*HID_;
    float* sW1 = sWs + 64*HID_;
    float* sFc = sW1 + HID_*HID_;      /* 32*32 */
    float* sB0 = sFc + HID_*HID_;
    float* sB1 = sB0 + HID_;
    float* sFb = sB1 + HID_;
    float* sx  = sFb + HID_;

    for (int t = threadIdx.x; t < 64*HID_; t += BDIM) { sW0[t] = w0[t]; sWs[t] = ws[t]; }
    for (int t = threadIdx.x; t < HID_*HID_; t += BDIM) { sW1[t] = w1[t]; sFc[t] = fcw[t]; }
    for (int t = threadIdx.x; t < HID_; t += BDIM) { sB0[t] = b0[t]; sB1[t] = b1[t]; sFb[t] = fcb[t]; }
    __syncthreads();

    int i = blockIdx.x*BDIM + threadIdx.x;
    if (i >= N) return;
    int tid = threadIdx.x;
    int gidx = g_gidx[i];

    const float* cellSrc = srcA ? g_cellA : g_cellB;

    const float4* np = reinterpret_cast<const float4*>(&g_net[(size_t)i*HID_]);
    const float4* pp = reinterpret_cast<const float4*>(&cellSrc[gidx*HID_]);
#pragma unroll
    for (int j = 0; j < 8; j++) {
        float4 a = np[j];
        sx[(4*j+0)*BDIM + tid] = a.x; sx[(4*j+1)*BDIM + tid] = a.y;
        sx[(4*j+2)*BDIM + tid] = a.z; sx[(4*j+3)*BDIM + tid] = a.w;
        float4 pb = pp[j];
        sx[(32+4*j+0)*BDIM + tid] = pb.x; sx[(32+4*j+1)*BDIM + tid] = pb.y;
        sx[(32+4*j+2)*BDIM + tid] = pb.z; sx[(32+4*j+3)*BDIM + tid] = pb.w;
    }

    float out[HID_];
    resblock_f32x2(sx, tid, sW0, sB0, sW1, sB1, sWs, out);

    /* c = out @ fc_c_w + fc_c_b (out in regs, fully unrolled, packed) */
    u64 c2[16];
    const u64* fb2 = reinterpret_cast<const u64*>(sFb);
#pragma unroll
    for (int j = 0; j < 16; j++) c2[j] = fb2[j];
#pragma unroll
    for (int k = 0; k < HID_; k++) {
        u64 ok2 = splat2(out[k]);
        const ulonglong2* r = reinterpret_cast<const ulonglong2*>(sFc + k*HID_);
#pragma unroll
        for (int j = 0; j < 8; j++) {
            ulonglong2 a = r[j];
            ffma2(c2[2*j+0], ok2, a.x);
            ffma2(c2[2*j+1], ok2, a.y);
        }
    }

    float* sp = &g_sums[gidx*HID_];
#pragma unroll
    for (int j = 0; j < 16; j++) {
        float lo, hi; unpack2(c2[j], lo, hi);
        atomicAdd(sp + 2*j + 0, lo);
        atomicAdd(sp + 2*j + 1, hi);
    }
    atomicAdd(&g_cnt[gidx], 1.0f);
}

/* -------- output: mean + transpose to [B, CDIM, G] -------- */
__global__ void output_kernel(float* __restrict__ out, int total) {
    int t = blockIdx.x*blockDim.x + threadIdx.x;
    if (t >= total) return;
    int g = t & (G_ - 1);
    int c = (t >> 15) & (HID_ - 1);
    int b = t >> 20;
    int bg = b*G_ + g;
    float cnt = fmaxf(g_cnt[bg], 1.0f);
    out[t] = g_sums[bg*HID_ + c] / cnt;
}

/* -------- host launcher -------- */
extern "C" void kernel_launch(void* const* d_in, const int* in_sizes, int n_in,
                              void* d_out, int out_size) {
    const float* p   = (const float*)d_in[0];
    const float* Wp  = (const float*)d_in[1];
    const float* Bp  = (const float*)d_in[2];
    const float* W0  = (const float*)d_in[3];
    const float* B0  = (const float*)d_in[4];
    const float* W1  = (const float*)d_in[5];
    const float* B1  = (const float*)d_in[6];
    const float* Ws  = (const float*)d_in[7];
    const float* Fc  = (const float*)d_in[8];
    const float* FcB = (const float*)d_in[9];
    float* out = (float*)d_out;

    int T = in_sizes[0] / (B_ * 3);
    int N = B_ * T;
    int nb = (N + BDIM - 1) / BDIM;

    const int P0_SMEM = (3840 + 2048 + 2048 + 1024 + 64 + 32 + 32 + 64*BDIM) * 4;
    const int PB_SMEM = (2048 + 2048 + 1024 + 32 + 32 + 64*BDIM) * 4;
    const int PF_SMEM = (2048 + 2048 + 1024 + 1024 + 32 + 32 + 32 + 64*BDIM) * 4;

    cudaFuncSetAttribute(point0_kernel, cudaFuncAttributeMaxDynamicSharedMemorySize, P0_SMEM);
    cudaFuncSetAttribute(pool_block_kernel, cudaFuncAttributeMaxDynamicSharedMemorySize, PB_SMEM);
    cudaFuncSetAttribute(final_kernel, cudaFuncAttributeMaxDynamicSharedMemorySize, PF_SMEM);

    /* block 0 + scatter into A */
    init_cells_kernel<<<512, 256>>>(0);
    point0_kernel<<<nb, BDIM, P0_SMEM>>>(p, Wp, Bp, W0, B0, W1, B1, Ws, T, N);

    /* block 1: read A -> write B */
    init_cells_kernel<<<512, 256>>>(1);
    pool_block_kernel<<<nb, BDIM, PB_SMEM>>>(W0 + 1*64*HID_, B0 + 1*HID_,
                                             W1 + 1*HID_*HID_, B1 + 1*HID_,
                                             Ws + 1*64*HID_, 1, N);
    /* block 2: read B -> write A */
    init_cells_kernel<<<512, 256>>>(0);
    pool_block_kernel<<<nb, BDIM, PB_SMEM>>>(W0 + 2*64*HID_, B0 + 2*HID_,
                                             W1 + 2*HID_*HID_, B1 + 2*HID_,
                                             Ws + 2*64*HID_, 0, N);
    /* block 3: read A -> write B */
    init_cells_kernel<<<512, 256>>>(1);
    pool_block_kernel<<<nb, BDIM, PB_SMEM>>>(W0 + 3*64*HID_, B0 + 3*HID_,
                                             W1 + 3*HID_*HID_, B1 + 3*HID_,
                                             Ws + 3*64*HID_, 1, N);
    /* block 4 + fc_c + scatter-mean: read B */
    clear_accum_kernel<<<512, 256>>>();
    final_kernel<<<nb, BDIM, PF_SMEM>>>(W0 + 4*64*HID_, B0 + 4*HID_,
                                        W1 + 4*HID_*HID_, B1 + 4*HID_,
                                        Ws + 4*64*HID_, Fc, FcB, 0, N);

    output_kernel<<<(out_size + 255)/256, 256>>>(out, out_size);
}

// round 3
// speedup vs baseline: 1.0366x; 1.0004x over previous
#include <cuda_runtime.h>
#include <float.h>
#include <math.h>

#define B_     2
#define RESO_  32
#define G_     (RESO_*RESO_*RESO_)     /* 32768 */
#define BG_    (B_*G_)                 /* 65536 */
#define HID_   32
#define NMAX_  524288
#define BDIM   128

typedef unsigned long long u64;

/* -------- packed f32x2 helpers (Blackwell FFMA2 path) -------- */
__device__ __forceinline__ u64 splat2(float v) {
    u64 r; asm("mov.b64 %0, {%1, %1};" : "=l"(r) : "f"(v)); return r;
}
__device__ __forceinline__ void unpack2(u64 v, float& lo, float& hi) {
    asm("mov.b64 {%0, %1}, %2;" : "=f"(lo), "=f"(hi) : "l"(v));
}
__device__ __forceinline__ void ffma2(u64& d, u64 a, u64 b) {
    asm("fma.rn.f32x2 %0, %1, %2, %0;" : "+l"(d) : "l"(a), "l"(b));
}

/* -------- scratch (static device globals: allocation-free) -------- */
__device__ float g_net[(size_t)NMAX_*HID_];   /* 64 MB */
__device__ int   g_gidx[NMAX_];
__device__ float g_cellA[BG_*HID_];           /* 8 MB */
__device__ float g_cellB[BG_*HID_];
__device__ float g_sums[BG_*HID_];
__device__ float g_cnt[BG_];

__device__ __forceinline__ void atomicMaxFloat(float* addr, float v) {
    v += 0.0f;                       /* canonicalize -0 -> +0 */
    if (v >= 0.0f) atomicMax((int*)addr, __float_as_int(v));
    else           atomicMin((unsigned int*)addr, __float_as_uint(v));
}

/* -------- init kernels -------- */
__global__ void init_cells_kernel(int which) {
    float* ptr = which ? g_cellB : g_cellA;
    int stride = gridDim.x * blockDim.x;
    for (int i = blockIdx.x*blockDim.x + threadIdx.x; i < BG_*HID_; i += stride)
        ptr[i] = -FLT_MAX;
}

__global__ void clear_accum_kernel() {
    int stride = gridDim.x * blockDim.x;
    for (int i = blockIdx.x*blockDim.x + threadIdx.x; i < BG_*HID_; i += stride)
        g_sums[i] = 0.0f;
    for (int i = blockIdx.x*blockDim.x + threadIdx.x; i < BG_; i += stride)
        g_cnt[i] = 0.0f;
}

/* -------- residual block (packed f32x2): x(64, smem transposed) -> out(32)
   h = relu( relu(x) @ W0 + b0 );  out = x @ Ws + ( h @ W1 + b1 )              */
__device__ __forceinline__ void resblock_f32x2(
    const float* sx, int tid,
    const float* __restrict__ sW0, const float* __restrict__ sB0,
    const float* __restrict__ sW1, const float* __restrict__ sB1,
    const float* __restrict__ sWs,
    float* out)
{
    u64 h2[16], o2[16];
    const u64* b0p = reinterpret_cast<const u64*>(sB0);
    const u64* b1p = reinterpret_cast<const u64*>(sB1);
#pragma unroll
    for (int j = 0; j < 16; j++) { h2[j] = b0p[j]; o2[j] = b1p[j]; }

#pragma unroll 4
    for (int k = 0; k < 64; k++) {
        float xk = sx[k*BDIM + tid];
        u64 xk2 = splat2(xk);
        u64 xr2 = splat2(fmaxf(xk, 0.0f));
        const ulonglong2* r0 = reinterpret_cast<const ulonglong2*>(sW0 + k*HID_);
        const ulonglong2* rs = reinterpret_cast<const ulonglong2*>(sWs + k*HID_);
#pragma unroll
        for (int j = 0; j < 8; j++) {
            ulonglong2 a = r0[j], s = rs[j];
            ffma2(h2[2*j+0], xr2, a.x);
            ffma2(h2[2*j+1], xr2, a.y);
            ffma2(o2[2*j+0], xk2, s.x);
            ffma2(o2[2*j+1], xk2, s.y);
        }
    }

    /* relu(h) stays in registers; W1 GEMV fully unrolled (no smem round-trip) */
    float hr[HID_];
#pragma unroll
    for (int j = 0; j < 16; j++) {
        float lo, hi; unpack2(h2[j], lo, hi);
        hr[2*j+0] = fmaxf(lo, 0.0f);
        hr[2*j+1] = fmaxf(hi, 0.0f);
    }
#pragma unroll
    for (int k = 0; k < HID_; k++) {
        u64 hk2 = splat2(hr[k]);
        const ulonglong2* r1 = reinterpret_cast<const ulonglong2*>(sW1 + k*HID_);
#pragma unroll
        for (int j = 0; j < 8; j++) {
            ulonglong2 a = r1[j];
            ffma2(o2[2*j+0], hk2, a.x);
            ffma2(o2[2*j+1], hk2, a.y);
        }
    }
#pragma unroll
    for (int j = 0; j < 16; j++) unpack2(o2[j], out[2*j], out[2*j+1]);
}

/* -------- stage 0: PE + fc_pos + resblock0 + scatter-max into cellA -------- */
__global__ void __launch_bounds__(BDIM) point0_kernel(
    const float* __restrict__ p,
    const float* __restrict__ Wp, const float* __restrict__ Bp,
    const float* __restrict__ w0, const float* __restrict__ b0,
    const float* __restrict__ w1, const float* __restrict__ b1,
    const float* __restrict__ ws,
    int T, int N)
{
    extern __shared__ float smem[];
    float* sWp = smem;                 /* 60*64 = 3840 */
    float* sW0 = sWp + 60*64;          /* 2048 */
    float* sWs = sW0 + 64*HID_;        /* 2048 */
    float* sW1 = sWs + 64*HID_;        /* 1024 */
    float* sBp = sW1 + HID_*HID_;      /* 64 */
    float* sB0 = sBp + 64;             /* 32 */
    float* sB1 = sB0 + HID_;           /* 32 */
    float* sx  = sB1 + HID_;           /* 64*BDIM */

    for (int t = threadIdx.x; t < 60*64; t += BDIM) sWp[t] = Wp[t];
    for (int t = threadIdx.x; t < 64*HID_; t += BDIM) { sW0[t] = w0[t]; sWs[t] = ws[t]; }
    for (int t = threadIdx.x; t < HID_*HID_; t += BDIM) sW1[t] = w1[t];
    for (int t = threadIdx.x; t < 64; t += BDIM) sBp[t] = Bp[t];
    for (int t = threadIdx.x; t < HID_; t += BDIM) { sB0[t] = b0[t]; sB1[t] = b1[t]; }
    __syncthreads();

    int i = blockIdx.x*BDIM + threadIdx.x;
    if (i >= N) return;
    int tid = threadIdx.x;

    float p0 = p[3*i+0], p1 = p[3*i+1], p2 = p[3*i+2];

    /* voxel index (match reference rounding exactly: IEEE div) */
    int b = i / T;
    float pn0 = fminf(fmaxf(__fdiv_rn(p0, 1.101f) + 0.5f, 0.0f), 0.999f);
    float pn1 = fminf(fmaxf(__fdiv_rn(p1, 1.101f) + 0.5f, 0.0f), 0.999f);
    float pn2 = fminf(fmaxf(__fdiv_rn(p2, 1.101f) + 0.5f, 0.0f), 0.999f);
    int xi0 = (int)floorf(pn0 * 32.0f);
    int xi1 = (int)floorf(pn1 * 32.0f);
    int xi2 = (int)floorf(pn2 * 32.0f);
    int gidx = xi0 + RESO_*(xi1 + RESO_*xi2) + b*G_;
    g_gidx[i] = gidx;

    /* x = PE(p) @ Wp + Bp -- fold sin/cos into the GEMV, packed accum */
    u64 x2[32];
    const u64* bp2 = reinterpret_cast<const u64*>(sBp);
#pragma unroll
    for (int j = 0; j < 32; j++) x2[j] = bp2[j];

    float q[3] = {2.0f*p0 - 1.0f, 2.0f*p1 - 1.0f, 2.0f*p2 - 1.0f};
#pragma unroll
    for (int d = 0; d < 3; d++) {
        float y = q[d];
#pragma unroll 1
        for (int l = 0; l < 10; l++) {
            float s, c;
            sincospif(y, &s, &c);   /* sin(pi * q * 2^l), exact range reduction */
            u64 s2 = splat2(s), c2 = splat2(c);
            const ulonglong2* rs_ = reinterpret_cast<const ulonglong2*>(sWp + (l*6 + d)*64);
            const ulonglong2* rc_ = reinterpret_cast<const ulonglong2*>(sWp + (l*6 + 3 + d)*64);
#pragma unroll
            for (int j = 0; j < 16; j++) {
                ulonglong2 a = rs_[j], bb = rc_[j];
                ffma2(x2[2*j+0], s2, a.x);
                ffma2(x2[2*j+1], s2, a.y);
                ffma2(x2[2*j+0], c2, bb.x);
                ffma2(x2[2*j+1], c2, bb.y);
            }
            y *= 2.0f;
        }
    }

#pragma unroll
    for (int j = 0; j < 32; j++) {
        float lo, hi; unpack2(x2[j], lo, hi);
        sx[(2*j+0)*BDIM + tid] = lo;
        sx[(2*j+1)*BDIM + tid] = hi;
    }

    float out[HID_];
    resblock_f32x2(sx, tid, sW0, sB0, sW1, sB1, sWs, out);

    float4* nw = reinterpret_cast<float4*>(&g_net[(size_t)i*HID_]);
#pragma unroll
    for (int j = 0; j < 8; j++)
        nw[j] = make_float4(out[4*j], out[4*j+1], out[4*j+2], out[4*j+3]);

    float* cd = &g_cellA[gidx*HID_];
#pragma unroll
    for (int j = 0; j < HID_; j++) atomicMaxFloat(cd + j, out[j]);
}

/* -------- stages 1..3: gather pooled + resblock + scatter-max -------- */
__global__ void __launch_bounds__(BDIM) pool_block_kernel(
    const float* __restrict__ w0, const float* __restrict__ b0,
    const float* __restrict__ w1, const float* __restrict__ b1,
    const float* __restrict__ ws,
    int srcA, int N)
{
    extern __shared__ float smem[];
    float* sW0 = smem;
    float* sWs = sW0 + 64*HID_;
    float* sW1 = sWs + 64*HID_;
    float* sB0 = sW1 + HID_*HID_;
    float* sB1 = sB0 + HID_;
    float* sx  = sB1 + HID_;

    for (int t = threadIdx.x; t < 64*HID_; t += BDIM) { sW0[t] = w0[t]; sWs[t] = ws[t]; }
    for (int t = threadIdx.x; t < HID_*HID_; t += BDIM) sW1[t] = w1[t];
    for (int t = threadIdx.x; t < HID_; t += BDIM) { sB0[t] = b0[t]; sB1[t] = b1[t]; }
    __syncthreads();

    int i = blockIdx.x*BDIM + threadIdx.x;
    if (i >= N) return;
    int tid = threadIdx.x;
    int gidx = g_gidx[i];

    const float* cellSrc = srcA ? g_cellA : g_cellB;
    float*       cellDst = srcA ? g_cellB : g_cellA;

    const float4* np = reinterpret_cast<const float4*>(&g_net[(size_t)i*HID_]);
    const float4* pp = reinterpret_cast<const float4*>(&cellSrc[gidx*HID_]);
#pragma unroll
    for (int j = 0; j < 8; j++) {
        float4 a = np[j];
        sx[(4*j+0)*BDIM + tid] = a.x; sx[(4*j+1)*BDIM + tid] = a.y;
        sx[(4*j+2)*BDIM + tid] = a.z; sx[(4*j+3)*BDIM + tid] = a.w;
        float4 pb = pp[j];
        sx[(32+4*j+0)*BDIM + tid] = pb.x; sx[(32+4*j+1)*BDIM + tid] = pb.y;
        sx[(32+4*j+2)*BDIM + tid] = pb.z; sx[(32+4*j+3)*BDIM + tid] = pb.w;
    }

    float out[HID_];
    resblock_f32x2(sx, tid, sW0, sB0, sW1, sB1, sWs, out);

    float4* nw = reinterpret_cast<float4*>(&g_net[(size_t)i*HID_]);
#pragma unroll
    for (int j = 0; j < 8; j++)
        nw[j] = make_float4(out[4*j], out[4*j+1], out[4*j+2], out[4*j+3]);

    float* cd = &cellDst[gidx*HID_];
#pragma unroll
    for (int j = 0; j < HID_; j++) atomicMaxFloat(cd + j, out[j]);
}

/* -------- stage 4: gather + resblock4 + fc_c + scatter-mean accum -------- */
__global__ void __launch_bounds__(BDIM) final_kernel(
    const float* __restrict__ w0, const float* __restrict__ b0,
    const float* __restrict__ w1, const float* __restrict__ b1,
    const float* __restrict__ ws,
    const float* __restrict__ fcw, const float* __restrict__ fcb,
    int srcA, int N)
{
    extern __shared__ float smem[];
    float* sW0 = smem;
    float* sWs = sW0 + 64*HID_;
    float* sW1 = sWs + 64*HID_;
    float* sFc = sW1 + HID_*HID_;      /* 32*32 */
    float* sB0 = sFc + HID_*HID_;
    float* sB1 = sB0 + HID_;
    float* sFb = sB1 + HID_;
    float* sx  = sFb + HID_;

    for (int t = threadIdx.x; t < 64*HID_; t += BDIM) { sW0[t] = w0[t]; sWs[t] = ws[t]; }
    for (int t = threadIdx.x; t < HID_*HID_; t += BDIM) { sW1[t] = w1[t]; sFc[t] = fcw[t]; }
    for (int t = threadIdx.x; t < HID_; t += BDIM) { sB0[t] = b0[t]; sB1[t] = b1[t]; sFb[t] = fcb[t]; }
    __syncthreads();

    int i = blockIdx.x*BDIM + threadIdx.x;
    if (i >= N) return;
    int tid = threadIdx.x;
    int gidx = g_gidx[i];

    const float* cellSrc = srcA ? g_cellA : g_cellB;

    const float4* np = reinterpret_cast<const float4*>(&g_net[(size_t)i*HID_]);
    const float4* pp = reinterpret_cast<const float4*>(&cellSrc[gidx*HID_]);
#pragma unroll
    for (int j = 0; j < 8; j++) {
        float4 a = np[j];
        sx[(4*j+0)*BDIM + tid] = a.x; sx[(4*j+1)*BDIM + tid] = a.y;
        sx[(4*j+2)*BDIM + tid] = a.z; sx[(4*j+3)*BDIM + tid] = a.w;
        float4 pb = pp[j];
        sx[(32+4*j+0)*BDIM + tid] = pb.x; sx[(32+4*j+1)*BDIM + tid] = pb.y;
        sx[(32+4*j+2)*BDIM + tid] = pb.z; sx[(32+4*j+3)*BDIM + tid] = pb.w;
    }

    float out[HID_];
    resblock_f32x2(sx, tid, sW0, sB0, sW1, sB1, sWs, out);

    /* c = out @ fc_c_w + fc_c_b (out in regs, fully unrolled, packed) */
    u64 c2[16];
    const u64* fb2 = reinterpret_cast<const u64*>(sFb);
#pragma unroll
    for (int j = 0; j < 16; j++) c2[j] = fb2[j];
#pragma unroll
    for (int k = 0; k < HID_; k++) {
        u64 ok2 = splat2(out[k]);
        const ulonglong2* r = reinterpret_cast<const ulonglong2*>(sFc + k*HID_);
#pragma unroll
        for (int j = 0; j < 8; j++) {
            ulonglong2 a = r[j];
            ffma2(c2[2*j+0], ok2, a.x);
            ffma2(c2[2*j+1], ok2, a.y);
        }
    }

    float* sp = &g_sums[gidx*HID_];
#pragma unroll
    for (int j = 0; j < 16; j++) {
        float lo, hi; unpack2(c2[j], lo, hi);
        atomicAdd(sp + 2*j + 0, lo);
        atomicAdd(sp + 2*j + 1, hi);
    }
    atomicAdd(&g_cnt[gidx], 1.0f);
}

/* -------- output: mean + transpose to [B, CDIM, G] -------- */
__global__ void output_kernel(float* __restrict__ out, int total) {
    int t = blockIdx.x*blockDim.x + threadIdx.x;
    if (t >= total) return;
    int g = t & (G_ - 1);
    int c = (t >> 15) & (HID_ - 1);
    int b = t >> 20;
    int bg = b*G_ + g;
    float cnt = fmaxf(g_cnt[bg], 1.0f);
    out[t] = g_sums[bg*HID_ + c] / cnt;
}

/* -------- host launcher -------- */
extern "C" void kernel_launch(void* const* d_in, const int* in_sizes, int n_in,
                              void* d_out, int out_size) {
    const float* p   = (const float*)d_in[0];
    const float* Wp  = (const float*)d_in[1];
    const float* Bp  = (const float*)d_in[2];
    const float* W0  = (const float*)d_in[3];
    const float* B0  = (const float*)d_in[4];
    const float* W1  = (const float*)d_in[5];
    const float* B1  = (const float*)d_in[6];
    const float* Ws  = (const float*)d_in[7];
    const float* Fc  = (const float*)d_in[8];
    const float* FcB = (const float*)d_in[9];
    float* out = (float*)d_out;

    int T = in_sizes[0] / (B_ * 3);
    int N = B_ * T;
    int nb = (N + BDIM - 1) / BDIM;

    const int P0_SMEM = (3840 + 2048 + 2048 + 1024 + 64 + 32 + 32 + 64*BDIM) * 4;
    const int PB_SMEM = (2048 + 2048 + 1024 + 32 + 32 + 64*BDIM) * 4;
    const int PF_SMEM = (2048 + 2048 + 1024 + 1024 + 32 + 32 + 32 + 64*BDIM) * 4;

    cudaFuncSetAttribute(point0_kernel, cudaFuncAttributeMaxDynamicSharedMemorySize, P0_SMEM);
    cudaFuncSetAttribute(pool_block_kernel, cudaFuncAttributeMaxDynamicSharedMemorySize, PB_SMEM);
    cudaFuncSetAttribute(final_kernel, cudaFuncAttributeMaxDynamicSharedMemorySize, PF_SMEM);

    /* block 0 + scatter into A */
    init_cells_kernel<<<512, 256>>>(0);
    point0_kernel<<<nb, BDIM, P0_SMEM>>>(p, Wp, Bp, W0, B0, W1, B1, Ws, T, N);

    /* block 1: read A -> write B */
    init_cells_kernel<<<512, 256>>>(1);
    pool_block_kernel<<<nb, BDIM, PB_SMEM>>>(W0 + 1*64*HID_, B0 + 1*HID_,
                                             W1 + 1*HID_*HID_, B1 + 1*HID_,
                                             Ws + 1*64*HID_, 1, N);
    /* block 2: read B -> write A */
    init_cells_kernel<<<512, 256>>>(0);
    pool_block_kernel<<<nb, BDIM, PB_SMEM>>>(W0 + 2*64*HID_, B0 + 2*HID_,
                                             W1 + 2*HID_*HID_, B1 + 2*HID_,
                                             Ws + 2*64*HID_, 0, N);
    /* block 3: read A -> write B */
    init_cells_kernel<<<512, 256>>>(1);
    pool_block_kernel<<<nb, BDIM, PB_SMEM>>>(W0 + 3*64*HID_, B0 + 3*HID_,
                                             W1 + 3*HID_*HID_, B1 + 3*HID_,
                                             Ws + 3*64*HID_, 1, N);
    /* block 4 + fc_c + scatter-mean: read B */
    clear_accum_kernel<<<512, 256>>>();
    final_kernel<<<nb, BDIM, PF_SMEM>>>(W0 + 4*64*HID_, B0 + 4*HID_,
                                        W1 + 4*HID_*HID_, B1 + 4*HID_,
                                        Ws + 4*64*HID_, Fc, FcB, 0, N);

    output_kernel<<<(out_size + 255)/256, 256>>>(out, out_size);
}